// round 15
// baseline (speedup 1.0000x reference)
#include <cuda_runtime.h>
#include <cuda_fp16.h>
#include <cstdint>

#define N_EL     19
#define GPC      4                   // graphs per CTA
#define ROWS     76                  // valid rows
#define MPAD     80                  // 5 m16 tiles
#define N_GRAPHS 1800
#define C        128
#define GRID     (N_GRAPHS / GPC)    // 450
#define NTHR     256

// pre-converted B image: [Wrel;Wroot] fp16, swizzled smem layout, 64 KB
__device__ __align__(16) char g_Bh[65536];

// smem map (bytes from dynamic base)
#define BOFF   0                     // B fp16: 8 k16-blocks x 256 rows x 32B
#define BBLK   8192
#define XOFF   65536                 // X fp16: 8 blocks x 80 rows x 32B
#define XBLK   2560
#define QOFF   0                     // Q fp32 (reuses B region): 76 x 528B
#define PQSTR  528
#define PTOFF  65536                 // P^T fp16 (reuses X): 4g x 2kb x 128r x 32B
#define AHOFF  98304                 // A fp16: 2 kb x 32 rows x 32B = 2KB
#define SMEM_BYTES 100352            // x2 CTAs = 200704

// ===========================================================================
// helpers
// ===========================================================================
__device__ __forceinline__ uint32_t s2u(const void* p) {
    uint32_t a;
    asm("{ .reg .u64 t; cvta.to.shared.u64 t, %1; cvt.u32.u64 %0, t; }"
        : "=r"(a) : "l"(p));
    return a;
}
__device__ __forceinline__ uint32_t h2(float a, float b) {
    __half2 t = __floats2half2_rn(a, b);     // a -> low half
    return *reinterpret_cast<uint32_t*>(&t);
}
__device__ __forceinline__ void sts16(uint32_t addr, uint32_t a, uint32_t b,
                                      uint32_t c, uint32_t d) {
    asm volatile("st.shared.v4.b32 [%0], {%1,%2,%3,%4};"
                 :: "r"(addr), "r"(a), "r"(b), "r"(c), "r"(d) : "memory");
}
__device__ __forceinline__ void sts8f(uint32_t addr, float a, float b) {
    asm volatile("st.shared.v2.f32 [%0], {%1,%2};"
                 :: "r"(addr), "f"(a), "f"(b) : "memory");
}
__device__ __forceinline__ void sts2h(uint32_t addr, float v) {
    __half h = __float2half_rn(v);
    uint16_t u = *reinterpret_cast<uint16_t*>(&h);
    asm volatile("st.shared.u16 [%0], %1;" :: "r"(addr), "h"(u) : "memory");
}
__device__ __forceinline__ float2 lds8f(uint32_t addr) {
    float2 v;
    asm volatile("ld.shared.v2.f32 {%0,%1}, [%2];"
                 : "=f"(v.x), "=f"(v.y) : "r"(addr));
    return v;
}
__device__ __forceinline__ void ldsm4(uint32_t addr, uint32_t& r0, uint32_t& r1,
                                      uint32_t& r2, uint32_t& r3) {
    asm volatile("ldmatrix.sync.aligned.m8n8.x4.shared.b16 {%0,%1,%2,%3}, [%4];"
                 : "=r"(r0), "=r"(r1), "=r"(r2), "=r"(r3) : "r"(addr));
}
__device__ __forceinline__ void mma_f16(float* d, uint32_t a0, uint32_t a1,
                                        uint32_t a2, uint32_t a3,
                                        uint32_t b0, uint32_t b1) {
    asm volatile(
        "mma.sync.aligned.m16n8k16.row.col.f32.f16.f16.f32 "
        "{%0,%1,%2,%3}, {%4,%5,%6,%7}, {%8,%9}, {%0,%1,%2,%3};"
        : "+f"(d[0]), "+f"(d[1]), "+f"(d[2]), "+f"(d[3])
        : "r"(a0), "r"(a1), "r"(a2), "r"(a3), "r"(b0), "r"(b1));
}
__device__ __forceinline__ void cpa16(uint32_t dst, const void* src) {
    asm volatile("cp.async.cg.shared.global [%0], [%1], 16;"
                 :: "r"(dst), "l"(src) : "memory");
}
#define CP_COMMIT() asm volatile("cp.async.commit_group;" ::: "memory")
#define CP_WAIT0()  asm volatile("cp.async.wait_group 0;" ::: "memory")

// 32B rows (16 fp16 = one k16 block), XOR-16B swizzle for conflict-free ldsm
__device__ __forceinline__ uint32_t rowoff(uint32_t r, uint32_t seg) {
    return (r * 32u + seg * 16u) ^ ((r & 4u) << 2);
}
// stage one (row, k16-block): 16 fp32 -> 16 fp16 as 2 x 16B granules
__device__ __forceinline__ void stage16h(uint32_t rowbase, int row,
                                         const float* f) {
    sts16(rowbase + rowoff((uint32_t)row, 0),
          h2(f[0], f[1]), h2(f[2], f[3]), h2(f[4], f[5]), h2(f[6], f[7]));
    sts16(rowbase + rowoff((uint32_t)row, 1),
          h2(f[8], f[9]), h2(f[10], f[11]), h2(f[12], f[13]), h2(f[14], f[15]));
}

// ===========================================================================
// Kernel 0 (one-shot, tiny): build swizzled fp16 image of [Wrel;Wroot]
// ===========================================================================
__global__ __launch_bounds__(256) void conv_b(const float* __restrict__ Wrel,
                                              const float* __restrict__ Wroot) {
    const int u = blockIdx.x * 256 + threadIdx.x;   // 2048 units
    const int n = u >> 3, c = u & 7;
    const float* src = (n < 128) ? Wrel  + (size_t)n * C
                                 : Wroot + (size_t)(n - 128) * C;
    const float4* s4 = (const float4*)(src + c * 16);
    float f[16];
    *(float4*)&f[0]  = s4[0];
    *(float4*)&f[4]  = s4[1];
    *(float4*)&f[8]  = s4[2];
    *(float4*)&f[12] = s4[3];
    char* base = g_Bh + (size_t)c * BBLK;
    *(uint4*)(base + rowoff((uint32_t)n, 0)) =
        make_uint4(h2(f[0], f[1]), h2(f[2], f[3]), h2(f[4], f[5]), h2(f[6], f[7]));
    *(uint4*)(base + rowoff((uint32_t)n, 1)) =
        make_uint4(h2(f[8], f[9]), h2(f[10], f[11]), h2(f[12], f[13]),
                   h2(f[14], f[15]));
}

// ===========================================================================
// Fused kernel (fp16 MMA everywhere):
//   MMA1: [P|Q](76x256) = X(76x128) @ [Wrel;Wroot]^T
//   MMA2: out_g = A(19x19) @ P_g + Q_g + b   (A fp16, P fp16, acc fp32)
// ===========================================================================
__global__ __launch_bounds__(NTHR, 2) void fused_kernel(
        const float* __restrict__ x,
        const float* __restrict__ ew,
        const float* __restrict__ brel,
        float* __restrict__ out) {
    extern __shared__ __align__(16) char smem[];
    const uint32_t sb = s2u(smem);

    const int tid  = threadIdx.x;
    const int wid  = tid >> 5;
    const int lane = tid & 31;
    const int blk  = blockIdx.x;

    // ---- B staging: linear 64KB cp.async memcpy (issued first)
#pragma unroll
    for (int q = 0; q < 16; q++) {
        const uint32_t off = (uint32_t)(tid * 16 + q * 4096);
        cpa16(sb + BOFF + off, g_Bh + off);
    }
    CP_COMMIT();

    // ---- build Ah: 32x32 fp16 (zero-padded), swizzled for ldmatrix
    for (int e = tid; e < 32 * 32; e += NTHR) {
        const int j = e >> 5, i = e & 31;
        float w = 0.0f;
        if (i < N_EL && j < N_EL && i != j) {
            const int r = (j < i) ? j : (j - 1);
            w = ew[i * (N_EL - 1) + r];
        }
        sts2h(sb + AHOFF + (uint32_t)((i >> 4) * 1024) + rowoff((uint32_t)j,
              (uint32_t)((i & 15) >> 3)) + (uint32_t)((i & 7) * 2), w);
    }

    // ---- stage X: 640 units (row 0..79, k16-block 0..7)
    for (int u = tid; u < MPAD * 8; u += NTHR) {
        const int row = u >> 3, c = u & 7;
        float f[16];
        if (row < ROWS) {
            const float4* s4 = (const float4*)(x + (size_t)(blk * ROWS + row) * C
                                               + c * 16);
            *(float4*)&f[0]  = s4[0];
            *(float4*)&f[4]  = s4[1];
            *(float4*)&f[8]  = s4[2];
            *(float4*)&f[12] = s4[3];
        } else {
#pragma unroll
            for (int q = 0; q < 16; q++) f[q] = 0.0f;
        }
        stage16h(sb + XOFF + (uint32_t)c * XBLK, row, f);
    }
    CP_WAIT0();
    __syncthreads();

    // ---- MMA1: warp covers n-cols [wid*32, +32), rows 0..79, K=128
    const int tt = lane >> 3;
    const int rr = lane & 7;
    const int fr = lane >> 2;
    const int fc = lane & 3;
    const uint32_t a_ld = rowoff((uint32_t)((tt & 1) * 8 + rr), (uint32_t)(tt >> 1));
    const uint32_t b_ld = rowoff((uint32_t)((tt >> 1) * 8 + rr), (uint32_t)(tt & 1));

    float acc[5][4][4];
#pragma unroll
    for (int mt = 0; mt < 5; mt++)
#pragma unroll
        for (int n8 = 0; n8 < 4; n8++)
#pragma unroll
            for (int q = 0; q < 4; q++)
                acc[mt][n8][q] = 0.0f;

#pragma unroll
    for (int c = 0; c < 8; c++) {
        uint32_t nb[4][2];
#pragma unroll
        for (int p = 0; p < 2; p++) {
            uint32_t r0, r1, r2, r3;
            ldsm4(sb + BOFF + (uint32_t)c * BBLK + (uint32_t)(wid * 1024 + p * 512)
                  + b_ld, r0, r1, r2, r3);
            nb[p * 2 + 0][0] = r0; nb[p * 2 + 0][1] = r1;
            nb[p * 2 + 1][0] = r2; nb[p * 2 + 1][1] = r3;
        }
#pragma unroll
        for (int mt = 0; mt < 5; mt++) {
            uint32_t a0, a1, a2, a3;
            ldsm4(sb + XOFF + (uint32_t)c * XBLK + (uint32_t)(mt * 512) + a_ld,
                  a0, a1, a2, a3);
#pragma unroll
            for (int n8 = 0; n8 < 4; n8++)
                mma_f16(acc[mt][n8], a0, a1, a2, a3, nb[n8][0], nb[n8][1]);
        }
    }
    __syncthreads();   // X/B reads done -> regions reusable (Pt / Q)

    // ---- writeback: warps 0-3 -> Pt fp16 transposed; warps 4-7 -> Q fp32
    if (wid < 4) {
#pragma unroll
        for (int mt = 0; mt < 5; mt++)
#pragma unroll
            for (int n8 = 0; n8 < 4; n8++) {
                const int c0 = wid * 32 + n8 * 8 + fc * 2;
#pragma unroll
                for (int half = 0; half < 2; half++) {
                    const int r = mt * 16 + fr + half * 8;
                    if (r < ROWS) {
                        const int g = (r * 27) >> 9;          // r / 19
                        const int i = r - g * 19;
                        const uint32_t base = sb + PTOFF
                            + (uint32_t)(g * 8192 + (i >> 4) * 4096)
                            + (uint32_t)((i & 7) * 2);
                        const uint32_t seg = (uint32_t)((i & 15) >> 3);
                        sts2h(base + rowoff((uint32_t)c0, seg),
                              acc[mt][n8][half * 2]);
                        sts2h(base + rowoff((uint32_t)(c0 + 1), seg),
                              acc[mt][n8][half * 2 + 1]);
                    }
                }
            }
    } else {
#pragma unroll
        for (int mt = 0; mt < 5; mt++)
#pragma unroll
            for (int n8 = 0; n8 < 4; n8++) {
                const int cq = (wid - 4) * 32 + n8 * 8 + fc * 2;
#pragma unroll
                for (int half = 0; half < 2; half++) {
                    const int r = mt * 16 + fr + half * 8;
                    if (r < ROWS)
                        sts8f(sb + QOFF + (uint32_t)(r * PQSTR) + (uint32_t)(cq * 4),
                              acc[mt][n8][half * 2], acc[mt][n8][half * 2 + 1]);
                }
            }
    }
    __syncthreads();

    // ---- MMA2: warp = (graph g, 64-col half nh); out = A@P + (Q + b)
    {
        const int g  = wid >> 1;
        const int nh = wid & 1;

        uint32_t af[2][2][4];
#pragma unroll
        for (int mt2 = 0; mt2 < 2; mt2++)
#pragma unroll
            for (int kb = 0; kb < 2; kb++)
                ldsm4(sb + AHOFF + (uint32_t)(kb * 1024 + mt2 * 512) + a_ld,
                      af[mt2][kb][0], af[mt2][kb][1], af[mt2][kb][2],
                      af[mt2][kb][3]);

        float d2[2][8][4];
#pragma unroll
        for (int n8 = 0; n8 < 8; n8++) {
            const int cg = nh * 64 + n8 * 8 + fc * 2;
            const float2 bv = *(const float2*)(brel + cg);
#pragma unroll
            for (int mt2 = 0; mt2 < 2; mt2++)
#pragma unroll
                for (int half = 0; half < 2; half++) {
                    const int j = mt2 * 16 + fr + half * 8;
                    if (j < N_EL) {
                        float2 q = lds8f(sb + QOFF
                                         + (uint32_t)((g * N_EL + j) * PQSTR)
                                         + (uint32_t)(cg * 4));
                        d2[mt2][n8][half * 2]     = q.x + bv.x;
                        d2[mt2][n8][half * 2 + 1] = q.y + bv.y;
                    } else {
                        d2[mt2][n8][half * 2] = 0.0f;
                        d2[mt2][n8][half * 2 + 1] = 0.0f;
                    }
                }
        }

#pragma unroll
        for (int kb = 0; kb < 2; kb++) {
            uint32_t pb[8][2];
#pragma unroll
            for (int p = 0; p < 4; p++) {
                uint32_t r0, r1, r2, r3;
                ldsm4(sb + PTOFF + (uint32_t)(g * 8192 + kb * 4096
                      + (nh * 64 + p * 16) * 32) + b_ld, r0, r1, r2, r3);
                pb[p * 2 + 0][0] = r0; pb[p * 2 + 0][1] = r1;
                pb[p * 2 + 1][0] = r2; pb[p * 2 + 1][1] = r3;
            }
#pragma unroll
            for (int mt2 = 0; mt2 < 2; mt2++)
#pragma unroll
                for (int n8 = 0; n8 < 8; n8++)
                    mma_f16(d2[mt2][n8], af[mt2][kb][0], af[mt2][kb][1],
                            af[mt2][kb][2], af[mt2][kb][3],
                            pb[n8][0], pb[n8][1]);
        }

        // store valid rows
#pragma unroll
        for (int mt2 = 0; mt2 < 2; mt2++)
#pragma unroll
            for (int n8 = 0; n8 < 8; n8++) {
                const int cg = nh * 64 + n8 * 8 + fc * 2;
#pragma unroll
                for (int half = 0; half < 2; half++) {
                    const int j = mt2 * 16 + fr + half * 8;
                    if (j < N_EL) {
                        float2 o = make_float2(d2[mt2][n8][half * 2],
                                               d2[mt2][n8][half * 2 + 1]);
                        *(float2*)(out + (size_t)(blk * ROWS + g * N_EL + j) * C
                                   + cg) = o;
                    }
                }
            }
    }
}

// ===========================================================================
// inputs (metadata order): x, edge_index, edge_weights, W_rel, b_rel, W_root
// ===========================================================================
extern "C" void kernel_launch(void* const* d_in, const int* in_sizes, int n_in,
                              void* d_out, int out_size) {
    const float* x     = (const float*)d_in[0];
    const float* ew    = (const float*)d_in[2];
    const float* Wrel  = (const float*)d_in[3];
    const float* brel  = (const float*)d_in[4];
    const float* Wroot = (const float*)d_in[5];
    float* out = (float*)d_out;

    cudaFuncSetAttribute(fused_kernel, cudaFuncAttributeMaxDynamicSharedMemorySize,
                         SMEM_BYTES);

    conv_b<<<8, 256>>>(Wrel, Wroot);
    fused_kernel<<<GRID, NTHR, SMEM_BYTES>>>(x, ew, brel, out);
}